// round 7
// baseline (speedup 1.0000x reference)
#include <cuda_runtime.h>
#include <cstdint>
#include <math.h>

// Problem constants
#define ROWS_TOTAL 16384          // B*T = 32*512
#define DDIM 2048                 // feature dim
#define KC 128                    // K per chunk
#define NCHUNK (DDIM / KC)        // 16
#define TILE_ROWS 32
#define NCTA (ROWS_TOTAL / TILE_ROWS)   // 512
#define NTHREADS 256

#define FEAT_PITCH 528                             // bytes per row in smem (512 + 16 pad)
#define SF_BYTES (TILE_ROWS * FEAT_PITCH)          // 16896
#define SW_BYTES 8192                              // 32 c4 x 16 j x 16B
#define STAGE_BYTES (SF_BYTES + SW_BYTES)          // 25088
#define NBUF 2
#define MBAR_OFF (NBUF * STAGE_BYTES)              // 50176
#define SMEM_BYTES (MBAR_OFF + 64)                 // 50240

#define BOXES_ELEMS (ROWS_TOTAL * 12)              // 196608
#define CONF_ELEMS  (ROWS_TOTAL * 3)               // 49152

// Packed weights: [c4 (512)][j (16)][kk (4)] floats; j=0..11 bbox, 12..14 conf, 15 pad=0
__device__ __align__(16) float g_wpack[512 * 16 * 4];

__device__ __forceinline__ uint32_t smem_u32(const void* p) {
    uint32_t a;
    asm("{ .reg .u64 t; cvta.to.shared.u64 t, %1; cvt.u32.u64 %0, t; }" : "=r"(a) : "l"(p));
    return a;
}

__global__ void prepack_kernel(const float* __restrict__ Wb, const float* __restrict__ Wc) {
    int idx = blockIdx.x * blockDim.x + threadIdx.x;   // 0 .. 32767
    if (idx < 512 * 64) {
        int c4 = idx >> 6;
        int j  = (idx >> 2) & 15;
        int kk = idx & 3;
        int k = c4 * 4 + kk;
        float v = 0.0f;
        if (j < 12)      v = Wb[k * 12 + j];
        else if (j < 15) v = Wc[k * 3 + (j - 12)];
        g_wpack[idx] = v;
    }
}

extern __shared__ char smem[];

__global__ void __launch_bounds__(NTHREADS, 4)
detector_main(const float* __restrict__ feat,
              const float* __restrict__ bb,     // b_bbox[12]
              const float* __restrict__ bc,     // b_conf[3]
              float* __restrict__ out,
              int writeConf, int writeValid)
{
    const int t = threadIdx.x;
    const int rowBase = blockIdx.x * TILE_ROWS;
    const int s    = t >> 5;          // warp id 0..7 -> k-group (warp-uniform)
    const int lane = t & 31;
    const int rg   = lane & 7;        // row group: owns rows rg, rg+8, rg+16, rg+24
    const int jq   = lane >> 3;       // j quarter: j0 = 4*jq
    const int j0   = jq * 4;
    const uint32_t smemBase = smem_u32(smem);
    const uint32_t mbarBase = smemBase + MBAR_OFF;

    // ---- mbarrier init: one per stage, 8 arrivals (one expect_tx per warp) ----
    if (t == 0) {
        #pragma unroll
        for (int b = 0; b < NBUF; ++b)
            asm volatile("mbarrier.init.shared.b64 [%0], 8;" :: "r"(mbarBase + b * 8) : "memory");
    }
    __syncthreads();

    // ---- bulk-async stage loader (TMA pipe; zero LSU cost) ----
    // warp w's lane 0 copies rows [w*4, w*4+4); warp 0 also copies weights.
    auto load_stage = [&](int chunk, int buf) {
        if (lane == 0) {
            const uint32_t base = smemBase + (uint32_t)buf * STAGE_BYTES;
            const uint32_t mbar = mbarBase + buf * 8;
            uint32_t bytes = 4 * 512 + (s == 0 ? SW_BYTES : 0);
            asm volatile("mbarrier.arrive.expect_tx.shared.b64 _, [%0], %1;"
                         :: "r"(mbar), "r"(bytes) : "memory");
            #pragma unroll
            for (int r = 0; r < 4; ++r) {
                int row = s * 4 + r;
                const float* src = feat + (size_t)(rowBase + row) * DDIM + chunk * KC;
                uint32_t dst = base + (uint32_t)row * FEAT_PITCH;
                asm volatile(
                    "cp.async.bulk.shared::cta.global.mbarrier::complete_tx::bytes "
                    "[%0], [%1], 512, [%2];"
                    :: "r"(dst), "l"(src), "r"(mbar) : "memory");
            }
            if (s == 0) {
                const float* wsrc = g_wpack + (size_t)chunk * 2048;   // 8KB slice
                asm volatile(
                    "cp.async.bulk.shared::cta.global.mbarrier::complete_tx::bytes "
                    "[%0], [%1], %2, [%3];"
                    :: "r"(base + SF_BYTES), "l"(wsrc), "r"((uint32_t)SW_BYTES), "r"(mbar)
                    : "memory");
            }
        }
    };

    // ---- accumulators: 4 rows x 4 j, packed f32x2 over K-pairs ----
    unsigned long long acc[4][4];
    #pragma unroll
    for (int d = 0; d < 4; ++d)
        #pragma unroll
        for (int j = 0; j < 4; ++j) acc[d][j] = 0ull;

    load_stage(0, 0);
    load_stage(1, 1);

    #pragma unroll 1
    for (int ch = 0; ch < NCHUNK; ++ch) {
        const int buf = ch & 1;
        const uint32_t mbar = mbarBase + buf * 8;
        const uint32_t parity = (uint32_t)((ch >> 1) & 1);
        // wait stage full (acquire) — per-thread; no extra barrier needed
        {
            uint32_t done;
            asm volatile(
                "{\n\t.reg .pred p;\n\t"
                "mbarrier.try_wait.parity.acquire.cta.shared::cta.b64 p, [%1], %2;\n\t"
                "selp.b32 %0, 1, 0, p;\n\t}"
                : "=r"(done) : "r"(mbar), "r"(parity) : "memory");
            if (!done) {
                asm volatile(
                    "{\n\t.reg .pred P1;\n\t"
                    "W_%=:\n\t"
                    "mbarrier.try_wait.parity.acquire.cta.shared::cta.b64 P1, [%0], %1, 0x989680;\n\t"
                    "@P1 bra.uni D_%=;\n\t"
                    "bra.uni W_%=;\n\t"
                    "D_%=:\n\t}"
                    :: "r"(mbar), "r"(parity) : "memory");
            }
        }

        const uint32_t base = smemBase + (uint32_t)buf * STAGE_BYTES;
        #pragma unroll
        for (int cc = 0; cc < 4; ++cc) {
            const int c4 = cc * 8 + s;                // warp-uniform k-group
            // weights first: 4x LDS.128, held in regs across the d-loop
            unsigned long long w[4][2];
            const uint32_t wa = base + SF_BYTES + (uint32_t)(c4 * 16 + j0) * 16u;
            #pragma unroll
            for (int j = 0; j < 4; ++j) {
                asm ("ld.shared.v2.u64 {%0,%1},[%2];"
                     : "=l"(w[j][0]), "=l"(w[j][1]) : "r"(wa + (uint32_t)(j * 16)));
            }
            // stream features per d (transient), FMA into acc
            const uint32_t fb0 = base + (uint32_t)(rg * FEAT_PITCH + c4 * 16);
            #pragma unroll
            for (int d = 0; d < 4; ++d) {
                unsigned long long fa0, fa1;
                asm ("ld.shared.v2.u64 {%0,%1},[%2];"
                     : "=l"(fa0), "=l"(fa1) : "r"(fb0 + (uint32_t)(d * 8 * FEAT_PITCH)));
                #pragma unroll
                for (int j = 0; j < 4; ++j) {
                    asm ("fma.rn.f32x2 %0,%1,%2,%0;" : "+l"(acc[d][j]) : "l"(fa0), "l"(w[j][0]));
                    asm ("fma.rn.f32x2 %0,%1,%2,%0;" : "+l"(acc[d][j]) : "l"(fa1), "l"(w[j][1]));
                }
            }
        }

        __syncthreads();   // all warps done reading buf -> safe to refill
        if (ch + 2 < NCHUNK) load_stage(ch + 2, buf);
    }

    // ---- reduce: collapse f32x2 halves, then across 8 warps via smem ----
    float val[4][4];
    #pragma unroll
    for (int d = 0; d < 4; ++d)
        #pragma unroll
        for (int j = 0; j < 4; ++j) {
            uint32_t lo, hi;
            asm ("mov.b64 {%0,%1},%2;" : "=r"(lo), "=r"(hi) : "l"(acc[d][j]));
            val[d][j] = __uint_as_float(lo) + __uint_as_float(hi);
        }

    float* sRed = reinterpret_cast<float*>(smem);          // [8 warps][32 rows][17]
    #pragma unroll
    for (int d = 0; d < 4; ++d)
        #pragma unroll
        for (int j = 0; j < 4; ++j)
            sRed[(s * TILE_ROWS + (rg + 8 * d)) * 17 + (j0 + j)] = val[d][j];
    __syncthreads();

    float* sOut = reinterpret_cast<float*>(smem + 8 * TILE_ROWS * 17 * 4);  // [32][17]
    {
        #pragma unroll
        for (int i = 0; i < 2; ++i) {
            int o = t + 256 * i;          // 0..511 covers 32x16
            int row = o >> 4, j = o & 15;
            float sum = 0.0f;
            #pragma unroll
            for (int ww = 0; ww < 8; ++ww) sum += sRed[(ww * TILE_ROWS + row) * 17 + j];
            sOut[row * 17 + j] = sum;
        }
    }
    __syncthreads();

    // ---- epilogue: bias + sigmoid + stable top-3 + threshold + stores ----
    if (t < TILE_ROWS) {
        float v[16];
        #pragma unroll
        for (int j = 0; j < 16; ++j) v[j] = sOut[t * 17 + j];

        float bx[12];
        #pragma unroll
        for (int j = 0; j < 12; ++j) bx[j] = v[j] + bb[j];
        float conf[3];
        #pragma unroll
        for (int a = 0; a < 3; ++a)
            conf[a] = 1.0f / (1.0f + expf(-(v[12 + a] + bc[a])));

        // stable descending sort of 3 (matches jax.lax.top_k tie-breaking)
        int i0 = 0, i1 = 1, i2 = 2, tmp;
        if (conf[i0] < conf[i1]) { tmp = i0; i0 = i1; i1 = tmp; }
        if (conf[i1] < conf[i2]) { tmp = i1; i1 = i2; i2 = tmp; }
        if (conf[i0] < conf[i1]) { tmp = i0; i0 = i1; i1 = tmp; }
        int ord[3] = { i0, i1, i2 };

        const int grow = rowBase + t;
        float4* bo = reinterpret_cast<float4*>(out);   // boxes: [row][3][4]
        #pragma unroll
        for (int slot = 0; slot < 3; ++slot) {
            int a = ord[slot];
            float c = conf[a];
            bool vld = c > 0.5f;
            float4 b4 = vld ? make_float4(bx[a * 4 + 0], bx[a * 4 + 1], bx[a * 4 + 2], bx[a * 4 + 3])
                            : make_float4(0.f, 0.f, 0.f, 0.f);
            bo[grow * 3 + slot] = b4;
            if (writeConf)  out[BOXES_ELEMS + grow * 3 + slot] = c;
            if (writeValid) out[BOXES_ELEMS + CONF_ELEMS + grow * 3 + slot] = vld ? 1.0f : 0.0f;
        }
    }
}

extern "C" void kernel_launch(void* const* d_in, const int* in_sizes, int n_in,
                              void* d_out, int out_size) {
    const float* feat = (const float*)d_in[0];   // [32,512,2048] f32
    const float* Wb   = (const float*)d_in[1];   // [2048,12]
    const float* bb   = (const float*)d_in[2];   // [12]
    const float* Wc   = (const float*)d_in[3];   // [2048,3]
    const float* bc   = (const float*)d_in[4];   // [3]
    float* out = (float*)d_out;

    cudaFuncSetAttribute(detector_main, cudaFuncAttributeMaxDynamicSharedMemorySize, SMEM_BYTES);

    prepack_kernel<<<64, 512>>>(Wb, Wc);

    int writeConf  = (out_size >= BOXES_ELEMS + CONF_ELEMS) ? 1 : 0;
    int writeValid = (out_size >= BOXES_ELEMS + 2 * CONF_ELEMS) ? 1 : 0;
    detector_main<<<NCTA, NTHREADS, SMEM_BYTES>>>(feat, bb, bc, out, writeConf, writeValid);
}

// round 8
// speedup vs baseline: 1.3242x; 1.3242x over previous
#include <cuda_runtime.h>
#include <cuda.h>
#include <cstdint>
#include <math.h>

// Problem constants
#define ROWS_TOTAL 16384          // B*T = 32*512
#define DDIM 2048                 // feature dim
#define KC 128                    // K per chunk (32 c4)
#define NCHUNK (DDIM / KC)        // 16
#define TILE_ROWS 32
#define NCTA (ROWS_TOTAL / TILE_ROWS)   // 512
#define NTHREADS 256

#define TILE_BYTES 4096                            // one TMA box: 32 rows x 128B (SW128)
#define SF_BYTES (4 * TILE_BYTES)                  // 16384 (4 boxes per chunk)
#define SW_BYTES 8192                              // 32 c4 x 16 slots x 16B
#define STAGE_BYTES (SF_BYTES + SW_BYTES)          // 24576 (1024-aligned)
#define NBUF 3
#define MBAR_OFF (NBUF * STAGE_BYTES)              // 73728
#define SMEM_BYTES (1024 + MBAR_OFF + 64)          // alignment slack + stages + mbars

#define BOXES_ELEMS (ROWS_TOTAL * 12)              // 196608
#define CONF_ELEMS  (ROWS_TOTAL * 3)               // 49152

// Packed weights, slot-transposed: [c4 (512)][slot m (16)][kk (4)] floats.
// Slot m holds output column j = 4*(m&3) + (m>>2); j=0..11 bbox, 12..14 conf, 15 pad.
__device__ __align__(16) float g_wpack[512 * 16 * 4];

__device__ __forceinline__ uint32_t smem_u32(const void* p) {
    uint32_t a;
    asm("{ .reg .u64 t; cvta.to.shared.u64 t, %1; cvt.u32.u64 %0, t; }" : "=r"(a) : "l"(p));
    return a;
}

__global__ void prepack_kernel(const float* __restrict__ Wb, const float* __restrict__ Wc) {
    int idx = blockIdx.x * blockDim.x + threadIdx.x;   // 0 .. 32767
    if (idx < 512 * 64) {
        int c4 = idx >> 6;
        int m  = (idx >> 2) & 15;
        int kk = idx & 3;
        int j  = 4 * (m & 3) + (m >> 2);   // transposed slot -> column
        int k  = c4 * 4 + kk;
        float v = 0.0f;
        if (j < 12)      v = Wb[k * 12 + j];
        else if (j < 15) v = Wc[k * 3 + (j - 12)];
        g_wpack[idx] = v;
    }
}

extern __shared__ char smem[];

__global__ void __launch_bounds__(NTHREADS, 3)
detector_main(const __grid_constant__ CUtensorMap tmap,
              const float* __restrict__ bb,     // b_bbox[12]
              const float* __restrict__ bc,     // b_conf[3]
              float* __restrict__ out,
              int writeConf, int writeValid)
{
    const int t = threadIdx.x;
    const int rowBase = blockIdx.x * TILE_ROWS;
    const int s    = t >> 5;          // warp id 0..7 -> cw within box (warp-uniform)
    const int lane = t & 31;
    const int rg   = lane & 7;        // row group: owns rows rg, rg+8, rg+16, rg+24
    const int jq   = lane >> 3;       // j quarter: owns j = 4*jq .. 4*jq+3
    const int j0   = jq * 4;
    const uint32_t rawBase = smem_u32(smem);
    const uint32_t smemBase = (rawBase + 1023u) & ~1023u;    // 1024-align for SW128 tiles
    const uint32_t mbarBase = smemBase + MBAR_OFF;

    // ---- mbarrier init: one per stage, 1 arrival (thread 0 issues everything) ----
    if (t == 0) {
        #pragma unroll
        for (int b = 0; b < NBUF; ++b)
            asm volatile("mbarrier.init.shared.b64 [%0], 1;" :: "r"(mbarBase + b * 8) : "memory");
    }
    __syncthreads();

    // ---- stage loader: 4 TMA 2D tensor boxes (features) + 1 bulk (weights) = 5 requests ----
    auto load_stage = [&](int chunk, int buf) {
        if (t == 0) {
            const uint32_t base = smemBase + (uint32_t)buf * STAGE_BYTES;
            const uint32_t mbar = mbarBase + buf * 8;
            asm volatile("mbarrier.arrive.expect_tx.shared.b64 _, [%0], %1;"
                         :: "r"(mbar), "r"((uint32_t)STAGE_BYTES) : "memory");
            #pragma unroll
            for (int tq = 0; tq < 4; ++tq) {
                int cx = chunk * KC + tq * 32;     // element coord in dim0
                asm volatile(
                    "cp.async.bulk.tensor.2d.shared::cta.global.tile.mbarrier::complete_tx::bytes "
                    "[%0], [%1, {%2, %3}], [%4];"
                    :: "r"(base + tq * TILE_BYTES), "l"(&tmap),
                       "r"(cx), "r"(rowBase), "r"(mbar) : "memory");
            }
            const float* wsrc = g_wpack + (size_t)chunk * 2048;   // 8KB slice
            asm volatile(
                "cp.async.bulk.shared::cta.global.mbarrier::complete_tx::bytes "
                "[%0], [%1], %2, [%3];"
                :: "r"(base + SF_BYTES), "l"(wsrc), "r"((uint32_t)SW_BYTES), "r"(mbar)
                : "memory");
        }
    };

    // ---- accumulators: 4 rows x 4 j, packed f32x2 over K-pairs ----
    unsigned long long acc[4][4];
    #pragma unroll
    for (int d = 0; d < 4; ++d)
        #pragma unroll
        for (int j = 0; j < 4; ++j) acc[d][j] = 0ull;

    load_stage(0, 0);
    load_stage(1, 1);

    const uint32_t fsw = (uint32_t)((s ^ rg) * 16);   // SW128 swizzled 16B slot for this lane

    #pragma unroll 1
    for (int ch = 0; ch < NCHUNK; ++ch) {
        const int buf = ch % NBUF;
        const uint32_t mbar = mbarBase + buf * 8;
        const uint32_t parity = (uint32_t)((ch / NBUF) & 1);
        // wait stage full (acquire)
        {
            uint32_t done;
            asm volatile(
                "{\n\t.reg .pred p;\n\t"
                "mbarrier.try_wait.parity.acquire.cta.shared::cta.b64 p, [%1], %2;\n\t"
                "selp.b32 %0, 1, 0, p;\n\t}"
                : "=r"(done) : "r"(mbar), "r"(parity) : "memory");
            if (!done) {
                asm volatile(
                    "{\n\t.reg .pred P1;\n\t"
                    "W_%=:\n\t"
                    "mbarrier.try_wait.parity.acquire.cta.shared::cta.b64 P1, [%0], %1, 0x989680;\n\t"
                    "@P1 bra.uni D_%=;\n\t"
                    "bra.uni W_%=;\n\t"
                    "D_%=:\n\t}"
                    :: "r"(mbar), "r"(parity) : "memory");
            }
        }
        __syncthreads();   // all threads finished compute(ch-1); buffer (ch+2)%3 is free

        if (ch + 2 < NCHUNK) load_stage(ch + 2, (ch + 2) % NBUF);

        const uint32_t base = smemBase + (uint32_t)buf * STAGE_BYTES;
        #pragma unroll
        for (int cc = 0; cc < 4; ++cc) {
            // features live in box cc; this warp reads 16B slot s of each row (swizzled)
            const uint32_t fb0 = base + (uint32_t)(cc * TILE_BYTES) + (uint32_t)(rg * 128) + fsw;
            // weights: c4 = cc*8+s; 4x LDS.128 at slots i*4+jq (conflict-free), held in regs
            unsigned long long w[4][2];
            const uint32_t wa = base + SF_BYTES + (uint32_t)((cc * 8 + s) * 256 + jq * 16);
            #pragma unroll
            for (int i = 0; i < 4; ++i) {
                asm ("ld.shared.v2.u64 {%0,%1},[%2];"
                     : "=l"(w[i][0]), "=l"(w[i][1]) : "r"(wa + (uint32_t)(i * 64)));
            }
            #pragma unroll
            for (int d = 0; d < 4; ++d) {
                unsigned long long fa0, fa1;
                asm ("ld.shared.v2.u64 {%0,%1},[%2];"
                     : "=l"(fa0), "=l"(fa1) : "r"(fb0 + (uint32_t)(d * 8 * 128)));
                #pragma unroll
                for (int i = 0; i < 4; ++i) {
                    asm ("fma.rn.f32x2 %0,%1,%2,%0;" : "+l"(acc[d][i]) : "l"(fa0), "l"(w[i][0]));
                    asm ("fma.rn.f32x2 %0,%1,%2,%0;" : "+l"(acc[d][i]) : "l"(fa1), "l"(w[i][1]));
                }
            }
        }
    }
    __syncthreads();   // done reading stage buffers before reuse as sRed

    // ---- reduce: collapse f32x2 halves, then across 8 warps via smem ----
    float val[4][4];
    #pragma unroll
    for (int d = 0; d < 4; ++d)
        #pragma unroll
        for (int j = 0; j < 4; ++j) {
            uint32_t lo, hi;
            asm ("mov.b64 {%0,%1},%2;" : "=r"(lo), "=r"(hi) : "l"(acc[d][j]));
            val[d][j] = __uint_as_float(lo) + __uint_as_float(hi);
        }

    float* sRed = reinterpret_cast<float*>(smem);          // [8 warps][32 rows][17]
    #pragma unroll
    for (int d = 0; d < 4; ++d)
        #pragma unroll
        for (int j = 0; j < 4; ++j)
            sRed[(s * TILE_ROWS + (rg + 8 * d)) * 17 + (j0 + j)] = val[d][j];
    __syncthreads();

    float* sOut = reinterpret_cast<float*>(smem + 8 * TILE_ROWS * 17 * 4);  // [32][17]
    {
        #pragma unroll
        for (int i = 0; i < 2; ++i) {
            int o = t + 256 * i;          // 0..511 covers 32x16
            int row = o >> 4, j = o & 15;
            float sum = 0.0f;
            #pragma unroll
            for (int ww = 0; ww < 8; ++ww) sum += sRed[(ww * TILE_ROWS + row) * 17 + j];
            sOut[row * 17 + j] = sum;
        }
    }
    __syncthreads();

    // ---- epilogue: bias + sigmoid + stable top-3 + threshold + stores ----
    if (t < TILE_ROWS) {
        float v[16];
        #pragma unroll
        for (int j = 0; j < 16; ++j) v[j] = sOut[t * 17 + j];

        float bx[12];
        #pragma unroll
        for (int j = 0; j < 12; ++j) bx[j] = v[j] + bb[j];
        float conf[3];
        #pragma unroll
        for (int a = 0; a < 3; ++a)
            conf[a] = 1.0f / (1.0f + expf(-(v[12 + a] + bc[a])));

        // stable descending sort of 3 (matches jax.lax.top_k tie-breaking)
        int i0 = 0, i1 = 1, i2 = 2, tmp;
        if (conf[i0] < conf[i1]) { tmp = i0; i0 = i1; i1 = tmp; }
        if (conf[i1] < conf[i2]) { tmp = i1; i1 = i2; i2 = tmp; }
        if (conf[i0] < conf[i1]) { tmp = i0; i0 = i1; i1 = tmp; }
        int ord[3] = { i0, i1, i2 };

        const int grow = rowBase + t;
        float4* bo = reinterpret_cast<float4*>(out);   // boxes: [row][3][4]
        #pragma unroll
        for (int slot = 0; slot < 3; ++slot) {
            int a = ord[slot];
            float c = conf[a];
            bool vld = c > 0.5f;
            float4 b4 = vld ? make_float4(bx[a * 4 + 0], bx[a * 4 + 1], bx[a * 4 + 2], bx[a * 4 + 3])
                            : make_float4(0.f, 0.f, 0.f, 0.f);
            bo[grow * 3 + slot] = b4;
            if (writeConf)  out[BOXES_ELEMS + grow * 3 + slot] = c;
            if (writeValid) out[BOXES_ELEMS + CONF_ELEMS + grow * 3 + slot] = vld ? 1.0f : 0.0f;
        }
    }
}

typedef CUresult (*EncodeTiledFn)(
    CUtensorMap*, CUtensorMapDataType, cuuint32_t, void*,
    const cuuint64_t*, const cuuint64_t*, const cuuint32_t*, const cuuint32_t*,
    CUtensorMapInterleave, CUtensorMapSwizzle, CUtensorMapL2promotion, CUtensorMapFloatOOBfill);

extern "C" void kernel_launch(void* const* d_in, const int* in_sizes, int n_in,
                              void* d_out, int out_size) {
    const float* feat = (const float*)d_in[0];   // [32,512,2048] f32
    const float* Wb   = (const float*)d_in[1];   // [2048,12]
    const float* bb   = (const float*)d_in[2];   // [12]
    const float* Wc   = (const float*)d_in[3];   // [2048,3]
    const float* bc   = (const float*)d_in[4];   // [3]
    float* out = (float*)d_out;

    // Build the feature tensor map (host-side, zero cost at graph replay)
    CUtensorMap tmap;
    {
        void* fn = nullptr;
        cudaDriverEntryPointQueryResult qres;
        cudaGetDriverEntryPoint("cuTensorMapEncodeTiled", &fn, cudaEnableDefault, &qres);
        EncodeTiledFn encode = (EncodeTiledFn)fn;
        cuuint64_t dims[2]    = { DDIM, ROWS_TOTAL };
        cuuint64_t strides[1] = { DDIM * sizeof(float) };
        cuuint32_t box[2]     = { 32, TILE_ROWS };        // 128B x 32 rows (SW128 legal)
        cuuint32_t estr[2]    = { 1, 1 };
        encode(&tmap, CU_TENSOR_MAP_DATA_TYPE_FLOAT32, 2, (void*)feat,
               dims, strides, box, estr,
               CU_TENSOR_MAP_INTERLEAVE_NONE, CU_TENSOR_MAP_SWIZZLE_128B,
               CU_TENSOR_MAP_L2_PROMOTION_L2_128B, CU_TENSOR_MAP_FLOAT_OOB_FILL_NONE);
    }

    cudaFuncSetAttribute(detector_main, cudaFuncAttributeMaxDynamicSharedMemorySize, SMEM_BYTES);

    prepack_kernel<<<64, 512>>>(Wb, Wc);

    int writeConf  = (out_size >= BOXES_ELEMS + CONF_ELEMS) ? 1 : 0;
    int writeValid = (out_size >= BOXES_ELEMS + 2 * CONF_ELEMS) ? 1 : 0;
    detector_main<<<NCTA, NTHREADS, SMEM_BYTES>>>(tmap, bb, bc, out, writeConf, writeValid);
}